// round 9
// baseline (speedup 1.0000x reference)
#include <cuda_runtime.h>
#include <mma.h>
#include <math.h>

using namespace nvcuda;

// Problem constants
constexpr int H_   = 16;
constexpr int D_   = 128;
constexpr int B_   = 2;
constexpr int S_   = 2048;
constexpr int DIM_ = 2048;
constexpr int EQKV = 3 * H_ * D_;   // 6144

// Scratch (device globals — allocation-free)
__device__ float g_qkv[(size_t)B_ * S_ * EQKV];        // [B,S,6144]
__device__ float g_attn[(size_t)B_ * S_ * H_ * D_];    // [B,S,2048]

// ---------------------------------------------------------------------------
// GEMM NT (tf32 wmma): C[M,N] = A[M,K] * B[N,K]^T   (A,B row-major, K-contig)
// Block tile 128x128, BK=16, 256 threads (8 warps), warp tile 32x64.
// Double-buffered SMEM staging: one __syncthreads per K-step; tile i+1 is
// staged into the alternate buffer while tile i feeds the MMAs.
// SMEM rows padded to 20 floats (80B) to break bank-conflict patterns in the
// wmma fragment loads (64B rows hit the same banks every row).
// ---------------------------------------------------------------------------
constexpr int BM = 128, BN = 128, BK = 16;
constexpr int BK_PAD = BK + 4;   // 20 floats/row; ldm=20 is a legal tf32 stride

__global__ __launch_bounds__(256) void gemm_nt_tf32(
    const float* __restrict__ A, const float* __restrict__ Bmat,
    float* __restrict__ C, int M, int N, int K)
{
    __shared__ float As[2][BM][BK_PAD];
    __shared__ float Bs[2][BN][BK_PAD];

    const int tid = threadIdx.x;
    const int w   = tid >> 5;
    const int wr  = w & 3;        // 4 warps along M (32 rows each)
    const int wc  = w >> 2;       // 2 warps along N (64 cols each)
    const int rowBase = blockIdx.y * BM;
    const int colBase = blockIdx.x * BN;

    // Per-thread staging coordinates (512 float4 per operand, 2 per thread).
    const int r0  = (tid + 0 * 256) >> 2;          // 0..63
    const int r1  = (tid + 1 * 256) >> 2;          // 64..127
    const int c4_ = (tid & 3) << 2;                // 0,4,8,12

    wmma::fragment<wmma::accumulator, 16, 16, 8, float> acc[2][4];
    #pragma unroll
    for (int i = 0; i < 2; i++)
        #pragma unroll
        for (int j = 0; j < 4; j++)
            wmma::fill_fragment(acc[i][j], 0.0f);

    auto stage = [&](int buf, int k0) {
        #pragma unroll
        for (int i = 0; i < 2; i++) {
            int r = (i == 0) ? r0 : r1;
            float4 va = *(const float4*)&A[(size_t)(rowBase + r) * K + k0 + c4_];
            As[buf][r][c4_ + 0] = wmma::__float_to_tf32(va.x);
            As[buf][r][c4_ + 1] = wmma::__float_to_tf32(va.y);
            As[buf][r][c4_ + 2] = wmma::__float_to_tf32(va.z);
            As[buf][r][c4_ + 3] = wmma::__float_to_tf32(va.w);
            float4 vb = *(const float4*)&Bmat[(size_t)(colBase + r) * K + k0 + c4_];
            Bs[buf][r][c4_ + 0] = wmma::__float_to_tf32(vb.x);
            Bs[buf][r][c4_ + 1] = wmma::__float_to_tf32(vb.y);
            Bs[buf][r][c4_ + 2] = wmma::__float_to_tf32(vb.z);
            Bs[buf][r][c4_ + 3] = wmma::__float_to_tf32(vb.w);
        }
    };

    stage(0, 0);
    __syncthreads();

    int cur = 0;
    for (int k0 = 0; k0 < K; k0 += BK) {
        // Stage next tile into the alternate buffer (overlaps with MMAs below).
        if (k0 + BK < K) stage(cur ^ 1, k0 + BK);

        #pragma unroll
        for (int kk = 0; kk < BK; kk += 8) {
            wmma::fragment<wmma::matrix_a, 16, 16, 8, wmma::precision::tf32, wmma::row_major> af[2];
            wmma::fragment<wmma::matrix_b, 16, 16, 8, wmma::precision::tf32, wmma::col_major> bf[4];
            #pragma unroll
            for (int i = 0; i < 2; i++)
                wmma::load_matrix_sync(af[i], &As[cur][wr * 32 + i * 16][kk], BK_PAD);
            #pragma unroll
            for (int j = 0; j < 4; j++)
                wmma::load_matrix_sync(bf[j], &Bs[cur][wc * 64 + j * 16][kk], BK_PAD);
            #pragma unroll
            for (int i = 0; i < 2; i++)
                #pragma unroll
                for (int j = 0; j < 4; j++)
                    wmma::mma_sync(acc[i][j], af[i], bf[j], acc[i][j]);
        }
        __syncthreads();   // readers done with cur; writers done with cur^1
        cur ^= 1;
    }

    #pragma unroll
    for (int i = 0; i < 2; i++)
        #pragma unroll
        for (int j = 0; j < 4; j++) {
            int r = rowBase + wr * 32 + i * 16;
            int c = colBase + wc * 64 + j * 16;
            wmma::store_matrix_sync(&C[(size_t)r * N + c], acc[i][j], N, wmma::mem_row_major);
        }
}

// ---------------------------------------------------------------------------
// Flash attention (tf32 wmma), non-causal. One CTA = one (b,h,q-tile of 64).
// Online softmax; O accumulator kept in SMEM (fp32) so per-row rescale is
// layout-safe with opaque wmma fragments.
// ---------------------------------------------------------------------------
constexpr int BQ = 64, BKV = 64;
constexpr size_t ATTN_SMEM =
    ((size_t)BQ * D_      // Qs
   + (size_t)BKV * D_     // Ks / Vs (reused)
   + (size_t)BQ * BKV     // Ss (scores -> P)
   + (size_t)BQ * D_      // Os
   + 3 * BQ) * sizeof(float);

__global__ __launch_bounds__(256) void attn_kernel(
    const float* __restrict__ qkv, float* __restrict__ out)
{
    extern __shared__ float sm[];
    float* Qs   = sm;                     // [BQ][128]
    float* Ks   = Qs + BQ * D_;           // [BKV][128]
    float* Ss   = Ks + BKV * D_;          // [BQ][64]
    float* Os   = Ss + BQ * BKV;          // [BQ][128]
    float* mrow = Os + BQ * D_;           // [BQ]
    float* lrow = mrow + BQ;
    float* arow = lrow + BQ;

    const int tid = threadIdx.x;
    const int w   = tid >> 5;
    const int qt  = blockIdx.x;
    const int h   = blockIdx.y;
    const int b   = blockIdx.z;
    const float* base = qkv + (size_t)b * S_ * EQKV;
    const float scale = 0.08838834764831845f;   // 1/sqrt(128)

    // Load Q tile (pre-scaled, tf32) and zero O.
    #pragma unroll
    for (int i = 0; i < 8; i++) {
        int lin = tid + i * 256;              // float4 index, 0..2047
        int r   = lin >> 5;                   // 0..63
        int c4  = (lin & 31) << 2;            // 0..124
        float4 v = *(const float4*)&base[(size_t)(qt * BQ + r) * EQKV + h * D_ + c4];
        Qs[r * D_ + c4 + 0] = wmma::__float_to_tf32(v.x * scale);
        Qs[r * D_ + c4 + 1] = wmma::__float_to_tf32(v.y * scale);
        Qs[r * D_ + c4 + 2] = wmma::__float_to_tf32(v.z * scale);
        Qs[r * D_ + c4 + 3] = wmma::__float_to_tf32(v.w * scale);
        float4 z = make_float4(0.f, 0.f, 0.f, 0.f);
        *(float4*)&Os[lin << 2] = z;
    }
    if (tid < BQ) { mrow[tid] = -INFINITY; lrow[tid] = 0.0f; }
    __syncthreads();

    for (int j = 0; j < S_ / BKV; j++) {
        const int kvBase = j * BKV;

        // Load K tile (tf32)
        #pragma unroll
        for (int i = 0; i < 8; i++) {
            int lin = tid + i * 256;
            int r   = lin >> 5;
            int c4  = (lin & 31) << 2;
            float4 v = *(const float4*)&base[(size_t)(kvBase + r) * EQKV + (H_ * D_) + h * D_ + c4];
            Ks[r * D_ + c4 + 0] = wmma::__float_to_tf32(v.x);
            Ks[r * D_ + c4 + 1] = wmma::__float_to_tf32(v.y);
            Ks[r * D_ + c4 + 2] = wmma::__float_to_tf32(v.z);
            Ks[r * D_ + c4 + 3] = wmma::__float_to_tf32(v.w);
        }
        __syncthreads();

        // S = Q K^T : warp w covers rows (w/2)*16, cols (w%2)*32
        {
            const int rB = (w >> 1) * 16;
            const int cB = (w & 1) * 32;
            wmma::fragment<wmma::accumulator, 16, 16, 8, float> sacc[2];
            wmma::fill_fragment(sacc[0], 0.0f);
            wmma::fill_fragment(sacc[1], 0.0f);
            #pragma unroll
            for (int kk = 0; kk < D_; kk += 8) {
                wmma::fragment<wmma::matrix_a, 16, 16, 8, wmma::precision::tf32, wmma::row_major> af;
                wmma::load_matrix_sync(af, &Qs[rB * D_ + kk], D_);
                #pragma unroll
                for (int jj = 0; jj < 2; jj++) {
                    wmma::fragment<wmma::matrix_b, 16, 16, 8, wmma::precision::tf32, wmma::col_major> bf;
                    wmma::load_matrix_sync(bf, &Ks[(cB + 16 * jj) * D_ + kk], D_);
                    wmma::mma_sync(sacc[jj], af, bf, sacc[jj]);
                }
            }
            #pragma unroll
            for (int jj = 0; jj < 2; jj++)
                wmma::store_matrix_sync(&Ss[rB * BKV + cB + 16 * jj], sacc[jj], BKV, wmma::mem_row_major);
        }
        __syncthreads();

        // Online softmax: 4 threads per row, 16 cols each.
        {
            const int r  = tid >> 2;
            const int q4 = tid & 3;
            float* srow = &Ss[r * BKV + q4 * 16];
            float tm = -INFINITY;
            #pragma unroll
            for (int c = 0; c < 16; c++) tm = fmaxf(tm, srow[c]);
            tm = fmaxf(tm, __shfl_xor_sync(0xFFFFFFFFu, tm, 1));
            tm = fmaxf(tm, __shfl_xor_sync(0xFFFFFFFFu, tm, 2));
            const float m_old = mrow[r];
            const float m_new = fmaxf(m_old, tm);
            float rs = 0.0f;
            #pragma unroll
            for (int c = 0; c < 16; c++) {
                float p = __expf(srow[c] - m_new);
                rs += p;
                srow[c] = wmma::__float_to_tf32(p);
            }
            rs += __shfl_xor_sync(0xFFFFFFFFu, rs, 1);
            rs += __shfl_xor_sync(0xFFFFFFFFu, rs, 2);
            if (q4 == 0) {
                float al = __expf(m_old - m_new);
                mrow[r] = m_new;
                lrow[r] = lrow[r] * al + rs;
                arow[r] = al;
            }
        }
        __syncthreads();

        // Scale O by per-row alpha; load V tile (into Ks buffer).
        #pragma unroll
        for (int i = 0; i < 8; i++) {
            int lin = tid + i * 256;
            int r   = lin >> 5;
            int c4  = (lin & 31) << 2;
            float al = arow[r];
            float4 o = *(float4*)&Os[lin << 2];
            o.x *= al; o.y *= al; o.z *= al; o.w *= al;
            *(float4*)&Os[lin << 2] = o;
            float4 v = *(const float4*)&base[(size_t)(kvBase + r) * EQKV + (2 * H_ * D_) + h * D_ + c4];
            Ks[r * D_ + c4 + 0] = wmma::__float_to_tf32(v.x);
            Ks[r * D_ + c4 + 1] = wmma::__float_to_tf32(v.y);
            Ks[r * D_ + c4 + 2] = wmma::__float_to_tf32(v.z);
            Ks[r * D_ + c4 + 3] = wmma::__float_to_tf32(v.w);
        }
        __syncthreads();

        // O += P @ V : warp w covers rows (w%4)*16, cols (w/4)*64.
        {
            const int rB = (w & 3) * 16;
            const int cB = (w >> 2) * 64;
            wmma::fragment<wmma::accumulator, 16, 16, 8, float> oacc[4];
            #pragma unroll
            for (int jj = 0; jj < 4; jj++)
                wmma::load_matrix_sync(oacc[jj], &Os[rB * D_ + cB + 16 * jj], D_, wmma::mem_row_major);
            #pragma unroll
            for (int kk = 0; kk < BKV; kk += 8) {
                wmma::fragment<wmma::matrix_a, 16, 16, 8, wmma::precision::tf32, wmma::row_major> af;
                wmma::load_matrix_sync(af, &Ss[rB * BKV + kk], BKV);
                #pragma unroll
                for (int jj = 0; jj < 4; jj++) {
                    wmma::fragment<wmma::matrix_b, 16, 16, 8, wmma::precision::tf32, wmma::row_major> bf;
                    wmma::load_matrix_sync(bf, &Ks[kk * D_ + cB + 16 * jj], D_);
                    wmma::mma_sync(oacc[jj], af, bf, oacc[jj]);
                }
            }
            #pragma unroll
            for (int jj = 0; jj < 4; jj++)
                wmma::store_matrix_sync(&Os[rB * D_ + cB + 16 * jj], oacc[jj], D_, wmma::mem_row_major);
        }
        __syncthreads();
    }

    // Normalize and write to g_attn [B,S,H*D]
    #pragma unroll
    for (int i = 0; i < 8; i++) {
        int lin = tid + i * 256;
        int r   = lin >> 5;
        int c4  = (lin & 31) << 2;
        float inv = 1.0f / lrow[r];
        float4 o = *(float4*)&Os[lin << 2];
        o.x *= inv; o.y *= inv; o.z *= inv; o.w *= inv;
        *(float4*)&out[(size_t)b * S_ * (H_ * D_) + (size_t)(qt * BQ + r) * (H_ * D_) + h * D_ + c4] = o;
    }
}

// ---------------------------------------------------------------------------
// Launch
// ---------------------------------------------------------------------------
extern "C" void kernel_launch(void* const* d_in, const int* in_sizes, int n_in,
                              void* d_out, int out_size)
{
    const float* x    = (const float*)d_in[0];
    const float* Wqkv = (const float*)d_in[1];
    const float* Wout = (const float*)d_in[2];
    float* out = (float*)d_out;

    float *qkv_ptr = nullptr, *attn_ptr = nullptr;
    cudaGetSymbolAddress((void**)&qkv_ptr, g_qkv);
    cudaGetSymbolAddress((void**)&attn_ptr, g_attn);
    cudaFuncSetAttribute(attn_kernel, cudaFuncAttributeMaxDynamicSharedMemorySize, (int)ATTN_SMEM);

    // 1) QKV projection: [4096,2048] x [6144,2048]^T
    gemm_nt_tf32<<<dim3(EQKV / BN, (B_ * S_) / BM), 256>>>(x, Wqkv, qkv_ptr, B_ * S_, EQKV, DIM_);

    // 2) Attention
    attn_kernel<<<dim3(S_ / BQ, H_, B_), 256, ATTN_SMEM>>>(qkv_ptr, attn_ptr);

    // 3) Output projection: [4096,2048] x [2048,2048]^T
    gemm_nt_tf32<<<dim3(DIM_ / BN, (B_ * S_) / BM), 256>>>(attn_ptr, Wout, out, B_ * S_, DIM_, DIM_);
}

// round 13
// speedup vs baseline: 1.8417x; 1.8417x over previous
#include <cuda_runtime.h>
#include <mma.h>
#include <math.h>
#include <stdint.h>

using namespace nvcuda;

// Problem constants
constexpr int H_   = 16;
constexpr int D_   = 128;
constexpr int B_   = 2;
constexpr int S_   = 2048;
constexpr int DIM_ = 2048;
constexpr int EQKV = 3 * H_ * D_;   // 6144

// Scratch (device globals — allocation-free)
__device__ float g_qkv[(size_t)B_ * S_ * EQKV];        // [B,S,6144]
__device__ float g_attn[(size_t)B_ * S_ * H_ * D_];    // [B,S,2048]

// ---------------------------------------------------------------------------
// Helpers: tf32 convert + raw mma.m16n8k8 tf32 (documented fragment layouts)
// ---------------------------------------------------------------------------
__device__ __forceinline__ float f2tf32(float x) {
    uint32_t u;
    asm("cvt.rna.tf32.f32 %0, %1;" : "=r"(u) : "f"(x));
    return __uint_as_float(u);
}

__device__ __forceinline__ void mma_tf32_16x8x8(
    float d[4], const float a[4], float b0, float b1)
{
    uint32_t a0 = __float_as_uint(a[0]), a1 = __float_as_uint(a[1]);
    uint32_t a2 = __float_as_uint(a[2]), a3 = __float_as_uint(a[3]);
    uint32_t bb0 = __float_as_uint(b0), bb1 = __float_as_uint(b1);
    asm volatile(
        "mma.sync.aligned.m16n8k8.row.col.f32.tf32.tf32.f32 "
        "{%0,%1,%2,%3}, {%4,%5,%6,%7}, {%8,%9}, {%0,%1,%2,%3};\n"
        : "+f"(d[0]), "+f"(d[1]), "+f"(d[2]), "+f"(d[3])
        : "r"(a0), "r"(a1), "r"(a2), "r"(a3), "r"(bb0), "r"(bb1));
}

// ---------------------------------------------------------------------------
// GEMM NT (tf32 wmma): C[M,N] = A[M,K] * B[N,K]^T  — unchanged from R9 (passed,
// tensor=42.6%). Double-buffered smem, BK_PAD=20 anti-conflict padding.
// ---------------------------------------------------------------------------
constexpr int BM = 128, BN = 128, BK = 16;
constexpr int BK_PAD = BK + 4;

__global__ __launch_bounds__(256) void gemm_nt_tf32(
    const float* __restrict__ A, const float* __restrict__ Bmat,
    float* __restrict__ C, int M, int N, int K)
{
    __shared__ float As[2][BM][BK_PAD];
    __shared__ float Bs[2][BN][BK_PAD];

    const int tid = threadIdx.x;
    const int w   = tid >> 5;
    const int wr  = w & 3;
    const int wc  = w >> 2;
    const int rowBase = blockIdx.y * BM;
    const int colBase = blockIdx.x * BN;

    const int r0  = (tid + 0 * 256) >> 2;
    const int r1  = (tid + 1 * 256) >> 2;
    const int c4_ = (tid & 3) << 2;

    wmma::fragment<wmma::accumulator, 16, 16, 8, float> acc[2][4];
    #pragma unroll
    for (int i = 0; i < 2; i++)
        #pragma unroll
        for (int j = 0; j < 4; j++)
            wmma::fill_fragment(acc[i][j], 0.0f);

    auto stage = [&](int buf, int k0) {
        #pragma unroll
        for (int i = 0; i < 2; i++) {
            int r = (i == 0) ? r0 : r1;
            float4 va = *(const float4*)&A[(size_t)(rowBase + r) * K + k0 + c4_];
            As[buf][r][c4_ + 0] = wmma::__float_to_tf32(va.x);
            As[buf][r][c4_ + 1] = wmma::__float_to_tf32(va.y);
            As[buf][r][c4_ + 2] = wmma::__float_to_tf32(va.z);
            As[buf][r][c4_ + 3] = wmma::__float_to_tf32(va.w);
            float4 vb = *(const float4*)&Bmat[(size_t)(colBase + r) * K + k0 + c4_];
            Bs[buf][r][c4_ + 0] = wmma::__float_to_tf32(vb.x);
            Bs[buf][r][c4_ + 1] = wmma::__float_to_tf32(vb.y);
            Bs[buf][r][c4_ + 2] = wmma::__float_to_tf32(vb.z);
            Bs[buf][r][c4_ + 3] = wmma::__float_to_tf32(vb.w);
        }
    };

    stage(0, 0);
    __syncthreads();

    int cur = 0;
    for (int k0 = 0; k0 < K; k0 += BK) {
        if (k0 + BK < K) stage(cur ^ 1, k0 + BK);

        #pragma unroll
        for (int kk = 0; kk < BK; kk += 8) {
            wmma::fragment<wmma::matrix_a, 16, 16, 8, wmma::precision::tf32, wmma::row_major> af[2];
            wmma::fragment<wmma::matrix_b, 16, 16, 8, wmma::precision::tf32, wmma::col_major> bf[4];
            #pragma unroll
            for (int i = 0; i < 2; i++)
                wmma::load_matrix_sync(af[i], &As[cur][wr * 32 + i * 16][kk], BK_PAD);
            #pragma unroll
            for (int j = 0; j < 4; j++)
                wmma::load_matrix_sync(bf[j], &Bs[cur][wc * 64 + j * 16][kk], BK_PAD);
            #pragma unroll
            for (int i = 0; i < 2; i++)
                #pragma unroll
                for (int j = 0; j < 4; j++)
                    wmma::mma_sync(acc[i][j], af[i], bf[j], acc[i][j]);
        }
        __syncthreads();
        cur ^= 1;
    }

    #pragma unroll
    for (int i = 0; i < 2; i++)
        #pragma unroll
        for (int j = 0; j < 4; j++) {
            int r = rowBase + wr * 32 + i * 16;
            int c = colBase + wc * 64 + j * 16;
            wmma::store_matrix_sync(&C[(size_t)r * N + c], acc[i][j], N, wmma::mem_row_major);
        }
}

// ---------------------------------------------------------------------------
// Flash attention v2: raw mma.m16n8k8 tf32, register-resident O + softmax.
// One CTA = (b, h, 64-row q-tile). 128 threads (4 warps), warp w owns rows
// [16w, 16w+16). Fragment layouts (g=lane/4, t=lane%4):
//   A: a0(g,t) a1(g+8,t) a2(g,t+4) a3(g+8,t+4)
//   B: b0(n=g,k=t) b1(n=g,k=t+4)
//   C: c0(g,2t) c1(g,2t+1) c2(g+8,2t) c3(g+8,2t+1)
// Per KV tile: 3 __syncthreads (vs 6), no O/S smem accumulator traffic.
// ---------------------------------------------------------------------------
constexpr int BQ = 64, BKV = 64;
constexpr int KPAD = 132;   // Ks row pad: B-frag addr (4g+t)%32 all distinct
constexpr int VPAD = 136;   // Vs row pad: B-frag addr (8t+g)%32 all distinct
constexpr int SPAD = 68;    // Ss row pad: A-frag addr (4g+t)%32 all distinct
constexpr size_t ATTN_SMEM =
    ((size_t)BKV * KPAD + (size_t)BKV * VPAD + (size_t)BQ * SPAD) * sizeof(float);

__global__ __launch_bounds__(128) void attn_kernel(
    const float* __restrict__ qkv, float* __restrict__ out)
{
    extern __shared__ float sm[];
    float* Ks = sm;                       // [64][KPAD] (also Q staging)
    float* Vs = Ks + BKV * KPAD;          // [64][VPAD]
    float* Ss = Vs + BKV * VPAD;          // [64][SPAD]

    const int tid  = threadIdx.x;
    const int lane = tid & 31;
    const int w    = tid >> 5;            // 0..3
    const int g    = lane >> 2;           // 0..7
    const int t    = lane & 3;            // 0..3
    const int qt = blockIdx.x, h = blockIdx.y, b = blockIdx.z;
    const float* base = qkv + (size_t)b * S_ * EQKV;
    const float scale = 0.08838834764831845f;   // 1/sqrt(128)

    // ---- Stage Q tile (scaled, tf32) into Ks, then lift A-frags to regs ----
    #pragma unroll
    for (int i = 0; i < 16; i++) {
        int lin = tid + i * 128;              // float4 id, 0..2047
        int r   = lin >> 5;                   // 0..63
        int c4  = (lin & 31) << 2;            // 0..124
        float4 v = *(const float4*)&base[(size_t)(qt * BQ + r) * EQKV + h * D_ + c4];
        float4 o;
        o.x = f2tf32(v.x * scale); o.y = f2tf32(v.y * scale);
        o.z = f2tf32(v.z * scale); o.w = f2tf32(v.w * scale);
        *(float4*)&Ks[r * KPAD + c4] = o;
    }
    __syncthreads();

    float qa[16][4];                          // Q A-frags: 16 k-steps of 8
    const int qr = w * 16 + g;
    #pragma unroll
    for (int s = 0; s < 16; s++) {
        int k0 = s * 8;
        qa[s][0] = Ks[qr * KPAD + k0 + t];
        qa[s][1] = Ks[(qr + 8) * KPAD + k0 + t];
        qa[s][2] = Ks[qr * KPAD + k0 + t + 4];
        qa[s][3] = Ks[(qr + 8) * KPAD + k0 + t + 4];
    }
    __syncthreads();                          // Ks about to be overwritten

    float o_[16][4];                          // O: 16 n-frags over D=128
    #pragma unroll
    for (int n = 0; n < 16; n++)
        #pragma unroll
        for (int v = 0; v < 4; v++) o_[n][v] = 0.0f;
    float m0 = -INFINITY, m1 = -INFINITY, l0 = 0.0f, l1 = 0.0f;

    for (int j = 0; j < S_ / BKV; j++) {
        const int kvBase = j * BKV;

        // ---- Load K and V tiles (tf32) ----
        #pragma unroll
        for (int i = 0; i < 16; i++) {
            int lin = tid + i * 128;
            int r   = lin >> 5;
            int c4  = (lin & 31) << 2;
            const float* kp = &base[(size_t)(kvBase + r) * EQKV + (H_ * D_) + h * D_ + c4];
            float4 kv = *(const float4*)kp;
            float4 ko;
            ko.x = f2tf32(kv.x); ko.y = f2tf32(kv.y);
            ko.z = f2tf32(kv.z); ko.w = f2tf32(kv.w);
            *(float4*)&Ks[r * KPAD + c4] = ko;
            const float* vp = &base[(size_t)(kvBase + r) * EQKV + (2 * H_ * D_) + h * D_ + c4];
            float4 vv = *(const float4*)vp;
            float4 vo;
            vo.x = f2tf32(vv.x); vo.y = f2tf32(vv.y);
            vo.z = f2tf32(vv.z); vo.w = f2tf32(vv.w);
            *(float4*)&Vs[r * VPAD + c4] = vo;
        }
        __syncthreads();

        // ---- S = Q K^T : sacc[8 n-frags][4], rows [16w,16w+16), cols 0..63 ----
        float sacc[8][4];
        #pragma unroll
        for (int n = 0; n < 8; n++)
            #pragma unroll
            for (int v = 0; v < 4; v++) sacc[n][v] = 0.0f;
        #pragma unroll
        for (int n = 0; n < 8; n++) {
            #pragma unroll
            for (int s = 0; s < 16; s++) {
                float b0 = Ks[(n * 8 + g) * KPAD + s * 8 + t];
                float b1 = Ks[(n * 8 + g) * KPAD + s * 8 + t + 4];
                mma_tf32_16x8x8(sacc[n], qa[s], b0, b1);
            }
        }

        // ---- Online softmax in registers (rows g and g+8 of this stripe) ----
        float mx0 = -INFINITY, mx1 = -INFINITY;
        #pragma unroll
        for (int n = 0; n < 8; n++) {
            mx0 = fmaxf(mx0, fmaxf(sacc[n][0], sacc[n][1]));
            mx1 = fmaxf(mx1, fmaxf(sacc[n][2], sacc[n][3]));
        }
        mx0 = fmaxf(mx0, __shfl_xor_sync(0xFFFFFFFFu, mx0, 1));
        mx0 = fmaxf(mx0, __shfl_xor_sync(0xFFFFFFFFu, mx0, 2));
        mx1 = fmaxf(mx1, __shfl_xor_sync(0xFFFFFFFFu, mx1, 1));
        mx1 = fmaxf(mx1, __shfl_xor_sync(0xFFFFFFFFu, mx1, 2));
        const float mn0 = fmaxf(m0, mx0);
        const float mn1 = fmaxf(m1, mx1);
        const float al0 = __expf(m0 - mn0);
        const float al1 = __expf(m1 - mn1);
        float rs0 = 0.0f, rs1 = 0.0f;
        #pragma unroll
        for (int n = 0; n < 8; n++) {
            float p0 = __expf(sacc[n][0] - mn0);
            float p1 = __expf(sacc[n][1] - mn0);
            float p2 = __expf(sacc[n][2] - mn1);
            float p3 = __expf(sacc[n][3] - mn1);
            rs0 += p0 + p1;  rs1 += p2 + p3;
            sacc[n][0] = f2tf32(p0); sacc[n][1] = f2tf32(p1);
            sacc[n][2] = f2tf32(p2); sacc[n][3] = f2tf32(p3);
        }
        rs0 += __shfl_xor_sync(0xFFFFFFFFu, rs0, 1);
        rs0 += __shfl_xor_sync(0xFFFFFFFFu, rs0, 2);
        rs1 += __shfl_xor_sync(0xFFFFFFFFu, rs1, 1);
        rs1 += __shfl_xor_sync(0xFFFFFFFFu, rs1, 2);
        l0 = l0 * al0 + rs0;  l1 = l1 * al1 + rs1;
        m0 = mn0;             m1 = mn1;

        // ---- Rescale register O by per-row alpha ----
        #pragma unroll
        for (int n = 0; n < 16; n++) {
            o_[n][0] *= al0; o_[n][1] *= al0;
            o_[n][2] *= al1; o_[n][3] *= al1;
        }

        // ---- C-layout P -> smem, then reload as A-frags ----
        #pragma unroll
        for (int n = 0; n < 8; n++) {
            *(float2*)&Ss[qr * SPAD + n * 8 + 2 * t]       = make_float2(sacc[n][0], sacc[n][1]);
            *(float2*)&Ss[(qr + 8) * SPAD + n * 8 + 2 * t] = make_float2(sacc[n][2], sacc[n][3]);
        }
        __syncthreads();

        float pa[8][4];
        #pragma unroll
        for (int s = 0; s < 8; s++) {
            int k0 = s * 8;
            pa[s][0] = Ss[qr * SPAD + k0 + t];
            pa[s][1] = Ss[(qr + 8) * SPAD + k0 + t];
            pa[s][2] = Ss[qr * SPAD + k0 + t + 4];
            pa[s][3] = Ss[(qr + 8) * SPAD + k0 + t + 4];
        }

        // ---- O += P V : 16 n-frags over D, 8 k-steps over KV ----
        #pragma unroll
        for (int n = 0; n < 16; n++) {
            #pragma unroll
            for (int s = 0; s < 8; s++) {
                float b0 = Vs[(s * 8 + t) * VPAD + n * 8 + g];
                float b1 = Vs[(s * 8 + t + 4) * VPAD + n * 8 + g];
                mma_tf32_16x8x8(o_[n], pa[s], b0, b1);
            }
        }
        __syncthreads();   // all reads of Ks/Vs/Ss done before next tile's stores
    }

    // ---- Normalize and write out (rows qr, qr+8; cols n*8+2t, +1) ----
    const float inv0 = 1.0f / l0, inv1 = 1.0f / l1;
    const size_t outBase = (size_t)b * S_ * (H_ * D_) + (size_t)h * D_;
    const size_t row0 = (size_t)(qt * BQ + qr) * (H_ * D_);
    const size_t row1 = (size_t)(qt * BQ + qr + 8) * (H_ * D_);
    #pragma unroll
    for (int n = 0; n < 16; n++) {
        int c = n * 8 + 2 * t;
        *(float2*)&out[outBase + row0 + c] = make_float2(o_[n][0] * inv0, o_[n][1] * inv0);
        *(float2*)&out[outBase + row1 + c] = make_float2(o_[n][2] * inv1, o_[n][3] * inv1);
    }
}

// ---------------------------------------------------------------------------
// Launch
// ---------------------------------------------------------------------------
extern "C" void kernel_launch(void* const* d_in, const int* in_sizes, int n_in,
                              void* d_out, int out_size)
{
    const float* x    = (const float*)d_in[0];
    const float* Wqkv = (const float*)d_in[1];
    const float* Wout = (const float*)d_in[2];
    float* out = (float*)d_out;

    float *qkv_ptr = nullptr, *attn_ptr = nullptr;
    cudaGetSymbolAddress((void**)&qkv_ptr, g_qkv);
    cudaGetSymbolAddress((void**)&attn_ptr, g_attn);
    cudaFuncSetAttribute(attn_kernel, cudaFuncAttributeMaxDynamicSharedMemorySize, (int)ATTN_SMEM);

    // 1) QKV projection: [4096,2048] x [6144,2048]^T
    gemm_nt_tf32<<<dim3(EQKV / BN, (B_ * S_) / BM), 256>>>(x, Wqkv, qkv_ptr, B_ * S_, EQKV, DIM_);

    // 2) Attention (raw-mma flash, register O)
    attn_kernel<<<dim3(S_ / BQ, H_, B_), 128, ATTN_SMEM>>>(qkv_ptr, attn_ptr);

    // 3) Output projection: [4096,2048] x [2048,2048]^T
    gemm_nt_tf32<<<dim3(DIM_ / BN, (B_ * S_) / BM), 256>>>(attn_ptr, Wout, out, B_ * S_, DIM_, DIM_);
}